// round 12
// baseline (speedup 1.0000x reference)
#include <cuda_runtime.h>
#include <math_constants.h>

// ---------------- Problem constants ----------------
#define ROWS      19456     // B*C*N = 16*19*64
#define INPUT_DIM 200
#define NF        101       // rfft bins
#define FFTW      208       // 2*NF padded to 208 (re/im interleaved)
#define VD        64        // VQ dim
#define NCB       8192      // codebook entries

#define SZ_X      (ROWS * INPUT_DIM)   // 38,912,000
#define SZ_PROJ   (NF * VD)            // 6,464
#define SZ_CB     (NCB * VD)           // 524,288

// ---------------- Device scratch (no allocations allowed) ----------------
__device__ float g_W[INPUT_DIM * FFTW];          // DFT matrix (cos / -sin, ortho scaled)
__device__ float g_fft[ROWS * FFTW];             // rfft output, re/im interleaved
__device__ float g_amp[ROWS * NF];
__device__ float g_phase[ROWS * NF];
__device__ float g_featT[2][VD * ROWS];          // [amp/phase][k][row]  (k-major!)
__device__ float g_cbnT[2][VD * NCB];            // normalized codebooks, k-major

// ---------------- K0: build DFT matrix (double-precision twiddles) ----------------
__global__ void build_w_kernel() {
    int i = blockIdx.x * blockDim.x + threadIdx.x;
    if (i >= INPUT_DIM * FFTW) return;
    int n = i / FFTW;
    int c = i % FFTW;
    int f = c >> 1;
    float val = 0.f;
    if (f < NF) {
        // angle = 2*pi*f*n/200 = pi * (f*n/100)
        double xa = (double)(n * f) / 100.0;
        double s, cs;
        sincospi(xa, &s, &cs);
        const double scale = 0.070710678118654752440; // 1/sqrt(200), ortho norm
        val = (c & 1) ? (float)(-s * scale) : (float)(cs * scale);
    }
    g_W[i] = val;
}

// ---------------- K1: normalize + transpose codebooks (one warp per entry) ----------------
__global__ void norm_cb_kernel(const float* __restrict__ cb_amp,
                               const float* __restrict__ cb_phase) {
    int which = blockIdx.y;
    const float* src = which ? cb_phase : cb_amp;
    int warp = threadIdx.x >> 5;
    int lane = threadIdx.x & 31;
    int m = blockIdx.x * 8 + warp;            // 1024 blocks * 8 warps = 8192
    float v0 = src[m * VD + lane];
    float v1 = src[m * VD + 32 + lane];
    float s = v0 * v0 + v1 * v1;
    #pragma unroll
    for (int o = 16; o; o >>= 1) s += __shfl_xor_sync(0xffffffffu, s, o);
    float nrm = sqrtf(s);
    float* dst = g_cbnT[which];
    dst[lane * NCB + m]        = v0 / nrm;
    dst[(lane + 32) * NCB + m] = v1 / nrm;
}

// ---------------- K2: DFT as tiled GEMM: g_fft = x[ROWS x 200] @ W[200 x 208] ----------------
// BM=64, BN=64 (4 col tiles, guard c<208), BK=40, 256 threads, 4x4 micro-tile
__global__ void dft_gemm_kernel(const float* __restrict__ x) {
    __shared__ float As[64 * 40];   // [m][k]
    __shared__ float Bs[40 * 64];   // [k][n]
    int tx = threadIdx.x & 15;
    int ty = threadIdx.x >> 4;
    int rowBase = blockIdx.x * 64;          // 304 * 64 = 19456 exact
    int colBase = blockIdx.y * 64;          // 0..255, guard 208
    float acc[4][4] = {};
    for (int kt = 0; kt < 5; ++kt) {
        int k0 = kt * 40;
        __syncthreads();
        for (int idx = threadIdx.x; idx < 64 * 40; idx += 256) {
            int mm = idx / 40, kk = idx - mm * 40;
            As[idx] = x[(rowBase + mm) * INPUT_DIM + k0 + kk];
        }
        for (int idx = threadIdx.x; idx < 40 * 64; idx += 256) {
            int kk = idx >> 6, nn = idx & 63;
            int c = colBase + nn;
            Bs[idx] = (c < FFTW) ? g_W[(k0 + kk) * FFTW + c] : 0.f;
        }
        __syncthreads();
        #pragma unroll 8
        for (int k = 0; k < 40; ++k) {
            float4 b = *reinterpret_cast<const float4*>(&Bs[k * 64 + tx * 4]);
            float bv[4] = {b.x, b.y, b.z, b.w};
            #pragma unroll
            for (int i = 0; i < 4; ++i) {
                float a = As[(ty * 4 + i) * 40 + k];
                #pragma unroll
                for (int j = 0; j < 4; ++j) acc[i][j] += a * bv[j];
            }
        }
    }
    #pragma unroll
    for (int i = 0; i < 4; ++i) {
        int r = rowBase + ty * 4 + i;
        #pragma unroll
        for (int j = 0; j < 4; ++j) {
            int c = colBase + tx * 4 + j;
            if (c < FFTW) g_fft[r * FFTW + c] = acc[i][j];
        }
    }
}

// ---------------- K3: amp / phase elementwise ----------------
__global__ void ampphase_kernel() {
    int i = blockIdx.x * blockDim.x + threadIdx.x;
    if (i >= ROWS * NF) return;
    int r = i / NF;
    int f = i - r * NF;
    float re = g_fft[r * FFTW + 2 * f];
    float im = g_fft[r * FFTW + 2 * f + 1];
    g_amp[i]   = sqrtf(re * re + im * im);
    g_phase[i] = atan2f(im, re);
}

// ---------------- K4: projection GEMM -> transposed features ----------------
// feat[r][d] = sum_k amp[r][k] * proj[k][d]; write featT[d][r].
// (L2 normalization of features is a positive per-row scale -> argmax-invariant -> skipped)
__global__ void proj_kernel(const float* __restrict__ proj_amp,
                            const float* __restrict__ proj_phase) {
    __shared__ float pjs[NF * VD];      // 101x64
    __shared__ float rows_s[4 * NF];    // 4 feature rows
    int y = blockIdx.y;
    const float* proj = y ? proj_phase : proj_amp;
    const float* src  = y ? g_phase : g_amp;
    int rowBase = blockIdx.x * 4;       // 4864 * 4 = 19456 exact
    for (int idx = threadIdx.x; idx < NF * VD; idx += 256) pjs[idx] = proj[idx];
    for (int idx = threadIdx.x; idx < 4 * NF; idx += 256)
        rows_s[idx] = src[rowBase * NF + idx];   // contiguous
    __syncthreads();
    int tx = threadIdx.x & 63;   // d
    int ty = threadIdx.x >> 6;   // row within block
    float acc = 0.f;
    #pragma unroll
    for (int k = 0; k < NF; ++k)
        acc += rows_s[ty * NF + k] * pjs[k * VD + tx];
    g_featT[y][tx * ROWS + rowBase + ty] = acc;
}

// ---------------- K5: fused score-GEMM + argmax ----------------
// For each row tile (128 rows), sweep all 8192 codebook cols in 64-wide tiles,
// keep running argmax in registers. BM=128, BN=64, K=64 staged once.
// smem: As[k][m] ld=128 (32KB) + Bs[k][n] ld=64 (16KB) = 48KB exactly.
__global__ void __launch_bounds__(256, 2)
score_kernel(float* __restrict__ out) {
    __shared__ float pool[12288];
    float* As = pool;            // 64*128
    float* Bs = pool + 8192;     // 64*64
    int cb = blockIdx.y;
    const float* featT = g_featT[cb];
    const float* cbnT  = g_cbnT[cb];
    int rowBase = blockIdx.x * 128;     // 152 * 128 = 19456 exact
    int tx = threadIdx.x & 15;          // col group (4 cols)
    int ty = threadIdx.x >> 4;          // row group (8 rows)

    // Load A tile (k-major feats): As[k*128 + m], vectorized, conflict-free
    for (int idx = threadIdx.x; idx < 64 * 128 / 4; idx += 256) {
        int k = idx >> 5, f4 = idx & 31;
        *reinterpret_cast<float4*>(&As[k * 128 + f4 * 4]) =
            *reinterpret_cast<const float4*>(&featT[k * ROWS + rowBase + f4 * 4]);
    }

    float best[8];
    int bidx[8];
    #pragma unroll
    for (int i = 0; i < 8; ++i) { best[i] = -CUDART_INF_F; bidx[i] = 0; }

    for (int t = 0; t < NCB / 64; ++t) {
        int colBase = t * 64;
        __syncthreads();   // also covers the As load on first iteration
        for (int idx = threadIdx.x; idx < 64 * 64 / 4; idx += 256) {
            int k = idx >> 4, f4 = idx & 15;
            *reinterpret_cast<float4*>(&Bs[k * 64 + f4 * 4]) =
                *reinterpret_cast<const float4*>(&cbnT[k * NCB + colBase + f4 * 4]);
        }
        __syncthreads();

        float acc[8][4] = {};
        #pragma unroll 8
        for (int k = 0; k < 64; ++k) {
            float4 a0 = *reinterpret_cast<const float4*>(&As[k * 128 + ty * 8]);
            float4 a1 = *reinterpret_cast<const float4*>(&As[k * 128 + ty * 8 + 4]);
            float4 b  = *reinterpret_cast<const float4*>(&Bs[k * 64 + tx * 4]);
            float av[8] = {a0.x, a0.y, a0.z, a0.w, a1.x, a1.y, a1.z, a1.w};
            float bv[4] = {b.x, b.y, b.z, b.w};
            #pragma unroll
            for (int i = 0; i < 8; ++i)
                #pragma unroll
                for (int j = 0; j < 4; ++j)
                    acc[i][j] += av[i] * bv[j];
        }
        // running argmax; strict '>' + increasing col order = first-max (jnp.argmax) semantics
        #pragma unroll
        for (int i = 0; i < 8; ++i)
            #pragma unroll
            for (int j = 0; j < 4; ++j) {
                float v = acc[i][j];
                if (v > best[i]) { best[i] = v; bidx[i] = colBase + tx * 4 + j; }
            }
    }

    // Cross-thread reduce (16 partials per row), reuse As region
    __syncthreads();
    float* sVal = pool;
    int*   sIdx = reinterpret_cast<int*>(pool + 2048);
    #pragma unroll
    for (int i = 0; i < 8; ++i) {
        int m = ty * 8 + i;
        sVal[m * 16 + tx] = best[i];
        sIdx[m * 16 + tx] = bidx[i];
    }
    __syncthreads();
    if (threadIdx.x < 128) {
        int m = threadIdx.x;
        float bv = sVal[m * 16];
        int   bi = sIdx[m * 16];
        #pragma unroll
        for (int t = 1; t < 16; ++t) {
            float v = sVal[m * 16 + t];
            int   id = sIdx[m * 16 + t];
            if (v > bv || (v == bv && id < bi)) { bv = v; bi = id; }
        }
        // __output__ hypothesis: float32 buffer; indices <= 8191 are exactly representable
        out[cb * ROWS + rowBase + m] = (float)bi;
    }
}

// ---------------- launch ----------------
extern "C" void kernel_launch(void* const* d_in, const int* in_sizes, int n_in,
                              void* d_out, int out_size) {
    // Robust input dispatch BY ELEMENT COUNT (immune to metadata ordering):
    //   x: 38,912,000   proj_*: 6,464 (amp first, then phase)   codebook_*: 524,288 (amp, phase)
    const float* x          = nullptr;
    const float* proj_amp   = nullptr;
    const float* proj_phase = nullptr;
    const float* cb_amp     = nullptr;
    const float* cb_phase   = nullptr;
    for (int i = 0; i < n_in; ++i) {
        const float* p = (const float*)d_in[i];
        int sz = in_sizes[i];
        if (sz == SZ_X) {
            x = p;
        } else if (sz == SZ_PROJ) {
            if (!proj_amp) proj_amp = p; else proj_phase = p;
        } else if (sz == SZ_CB) {
            if (!cb_amp) cb_amp = p; else cb_phase = p;
        }
    }
    float* out = (float*)d_out;

    build_w_kernel<<<(INPUT_DIM * FFTW + 255) / 256, 256>>>();
    norm_cb_kernel<<<dim3(NCB / 8, 2), 256>>>(cb_amp, cb_phase);
    dft_gemm_kernel<<<dim3(ROWS / 64, 4), 256>>>(x);
    ampphase_kernel<<<(ROWS * NF + 255) / 256, 256>>>();
    proj_kernel<<<dim3(ROWS / 4, 2), 256>>>(proj_amp, proj_phase);
    score_kernel<<<dim3(ROWS / 128, 2), 256>>>(out);
}

// round 14
// speedup vs baseline: 1.5424x; 1.5424x over previous
#include <cuda_runtime.h>
#include <cuda_bf16.h>
#include <math_constants.h>
#include <cstdint>

// ---------------- Problem constants ----------------
#define ROWS      19456     // B*C*N = 16*19*64
#define INPUT_DIM 200
#define NF        101       // rfft bins
#define FFTW      208       // 2*NF padded (re/im interleaved)
#define VD        64        // VQ dim
#define NCB       8192      // codebook entries

#define SZ_X      (ROWS * INPUT_DIM)
#define SZ_PROJ   (NF * VD)
#define SZ_CB     (NCB * VD)

// ---------------- Device scratch ----------------
__device__ float g_W[INPUT_DIM * FFTW];
__device__ float g_fft[ROWS * FFTW];
__device__ float g_amp[ROWS * NF];
__device__ float g_phase[ROWS * NF];
__device__ float g_featR[2][ROWS * VD];              // fp32 features row-major (exact fixup)
__device__ float g_cbnR[2][NCB * VD];                // normalized codebooks fp32 (fixup)
__device__ __nv_bfloat16 g_featS[2][ROWS * 128];     // [row][ah(64)|am(64)]
__device__ __nv_bfloat16 g_cbS[2][NCB * 128];        // [n][bh(64)|bm(64)]

// ============ base-ISA asm helpers (sm_80+) ============
__device__ __forceinline__ uint32_t smem_u32(const void* p) {
    uint32_t a;
    asm("{ .reg .u64 t; cvta.to.shared.u64 t, %1; cvt.u32.u64 %0, t; }" : "=r"(a) : "l"(p));
    return a;
}
#define CP_ASYNC16(dst, src) \
    asm volatile("cp.async.ca.shared.global [%0], [%1], 16;" :: "r"(dst), "l"(src))
#define CP_COMMIT() asm volatile("cp.async.commit_group;" ::: "memory")
#define CP_WAIT(n)  asm volatile("cp.async.wait_group %0;" :: "n"(n) : "memory")
#define LDSM_X4(r, addr) \
    asm volatile("ldmatrix.sync.aligned.m8n8.x4.shared.b16 {%0,%1,%2,%3}, [%4];" \
        : "=r"((r)[0]), "=r"((r)[1]), "=r"((r)[2]), "=r"((r)[3]) : "r"(addr))
#define MMA16816(d, a, b0, b1) \
    asm volatile("mma.sync.aligned.m16n8k16.row.col.f32.bf16.bf16.f32 " \
        "{%0,%1,%2,%3}, {%4,%5,%6,%7}, {%8,%9}, {%0,%1,%2,%3};" \
        : "+f"((d)[0]), "+f"((d)[1]), "+f"((d)[2]), "+f"((d)[3]) \
        : "r"((a)[0]), "r"((a)[1]), "r"((a)[2]), "r"((a)[3]), "r"(b0), "r"(b1))

// ---------------- K0: DFT matrix (fp64 twiddles) ----------------
__global__ void build_w_kernel() {
    int i = blockIdx.x * blockDim.x + threadIdx.x;
    if (i >= INPUT_DIM * FFTW) return;
    int n = i / FFTW, c = i % FFTW, f = c >> 1;
    float val = 0.f;
    if (f < NF) {
        double s, cs;
        sincospi((double)(n * f) / 100.0, &s, &cs);
        const double scale = 0.070710678118654752440;  // 1/sqrt(200)
        val = (c & 1) ? (float)(-s * scale) : (float)(cs * scale);
    }
    g_W[i] = val;
}

// ---------------- K1: normalize + bf16 2-way split codebooks ----------------
__global__ void norm_cb_kernel(const float* __restrict__ cb_amp,
                               const float* __restrict__ cb_phase) {
    int which = blockIdx.y;
    const float* src = which ? cb_phase : cb_amp;
    int warp = threadIdx.x >> 5, lane = threadIdx.x & 31;
    int m = blockIdx.x * 8 + warp;
    float v0 = src[m * VD + lane];
    float v1 = src[m * VD + 32 + lane];
    float s = v0 * v0 + v1 * v1;
    #pragma unroll
    for (int o = 16; o; o >>= 1) s += __shfl_xor_sync(0xffffffffu, s, o);
    float inv = 1.f / sqrtf(s);
    float n0 = v0 * inv, n1 = v1 * inv;
    g_cbnR[which][m * VD + lane]      = n0;
    g_cbnR[which][m * VD + 32 + lane] = n1;
    #pragma unroll
    for (int half = 0; half < 2; ++half) {
        float a = half ? n1 : n0;
        int k = lane + half * 32;
        __nv_bfloat16 h = __float2bfloat16(a);
        __nv_bfloat16 mid = __float2bfloat16(a - __bfloat162float(h));
        g_cbS[which][m * 128 + k]      = h;
        g_cbS[which][m * 128 + 64 + k] = mid;
    }
}

// ---------------- K2: DFT GEMM (fp32 FFMA) ----------------
__global__ void dft_gemm_kernel(const float* __restrict__ x) {
    __shared__ float As[64 * 40];
    __shared__ float Bs[40 * 64];
    int tx = threadIdx.x & 15, ty = threadIdx.x >> 4;
    int rowBase = blockIdx.x * 64, colBase = blockIdx.y * 64;
    float acc[4][4] = {};
    for (int kt = 0; kt < 5; ++kt) {
        int k0 = kt * 40;
        __syncthreads();
        for (int idx = threadIdx.x; idx < 64 * 40; idx += 256) {
            int mm = idx / 40, kk = idx - mm * 40;
            As[idx] = x[(rowBase + mm) * INPUT_DIM + k0 + kk];
        }
        for (int idx = threadIdx.x; idx < 40 * 64; idx += 256) {
            int kk = idx >> 6, nn = idx & 63;
            int c = colBase + nn;
            Bs[idx] = (c < FFTW) ? g_W[(k0 + kk) * FFTW + c] : 0.f;
        }
        __syncthreads();
        #pragma unroll 8
        for (int k = 0; k < 40; ++k) {
            float4 b = *reinterpret_cast<const float4*>(&Bs[k * 64 + tx * 4]);
            float bv[4] = {b.x, b.y, b.z, b.w};
            #pragma unroll
            for (int i = 0; i < 4; ++i) {
                float a = As[(ty * 4 + i) * 40 + k];
                #pragma unroll
                for (int j = 0; j < 4; ++j) acc[i][j] += a * bv[j];
            }
        }
    }
    #pragma unroll
    for (int i = 0; i < 4; ++i) {
        int r = rowBase + ty * 4 + i;
        #pragma unroll
        for (int j = 0; j < 4; ++j) {
            int c = colBase + tx * 4 + j;
            if (c < FFTW) g_fft[r * FFTW + c] = acc[i][j];
        }
    }
}

// ---------------- K3: amp / phase ----------------
__global__ void ampphase_kernel() {
    int i = blockIdx.x * blockDim.x + threadIdx.x;
    if (i >= ROWS * NF) return;
    int r = i / NF, f = i - r * NF;
    float re = g_fft[r * FFTW + 2 * f];
    float im = g_fft[r * FFTW + 2 * f + 1];
    g_amp[i]   = sqrtf(re * re + im * im);
    g_phase[i] = atan2f(im, re);
}

// ---------------- K4: projection -> featR (fp32) + featS (bf16 split) ----------------
__global__ void proj_kernel(const float* __restrict__ proj_amp,
                            const float* __restrict__ proj_phase) {
    __shared__ float pjs[NF * VD];
    __shared__ float rows_s[4 * NF];
    int y = blockIdx.y;
    const float* proj = y ? proj_phase : proj_amp;
    const float* src  = y ? g_phase : g_amp;
    int rowBase = blockIdx.x * 4;
    for (int idx = threadIdx.x; idx < NF * VD; idx += 256) pjs[idx] = proj[idx];
    for (int idx = threadIdx.x; idx < 4 * NF; idx += 256)
        rows_s[idx] = src[rowBase * NF + idx];
    __syncthreads();
    int tx = threadIdx.x & 63, ty = threadIdx.x >> 6;
    float acc = 0.f;
    #pragma unroll
    for (int k = 0; k < NF; ++k)
        acc += rows_s[ty * NF + k] * pjs[k * VD + tx];
    int row = rowBase + ty;
    g_featR[y][row * VD + tx] = acc;
    __nv_bfloat16 h = __float2bfloat16(acc);
    __nv_bfloat16 mid = __float2bfloat16(acc - __bfloat162float(h));
    g_featS[y][row * 128 + tx]      = h;
    g_featS[y][row * 128 + 64 + tx] = mid;
}

// ---------------- K5: HMMA bf16-split score GEMM + fused top2 + exact fp32 fixup ----
// BM=128 rows, sweep 64 tiles of BN=128 codewords. K=192 effective
// (ah*bh + ah*bm + am*bh), 12 mma k-steps. 8 warps = 4(m) x 2(n);
// warp tile 32x64; per-thread top2 over its 16-col slice per row; 16
// candidates/row re-scored exactly in fp32 (matches R12's proven semantics).
#define SM_TILE 34816            // 128 rows * 272B (136 bf16, padded)
#define SM_DYN  (3 * SM_TILE)    // A + 2 B buffers = 104448

__global__ void __launch_bounds__(256)
score_kernel(float* __restrict__ out) {
    extern __shared__ __align__(16) unsigned char dyn[];
    const int tid = threadIdx.x;
    const int lane = tid & 31, w = tid >> 5;
    const int wm = w & 3, wn = w >> 2;
    const int g = lane >> 2, t4 = lane & 3;
    const int cb = blockIdx.y;
    const int rowBase = blockIdx.x * 128;

    const uint32_t smA = smem_u32(dyn);
    const uint32_t smB0 = smA + SM_TILE;

    // ---- stage A (128 rows x 128 bf16, padded stride 272B) ----
    {
        const uint4* src = reinterpret_cast<const uint4*>(&g_featS[cb][(size_t)rowBase * 128]);
        for (int i = tid; i < 128 * 16; i += 256) {
            int r = i >> 4, c = i & 15;
            *reinterpret_cast<uint4*>(dyn + r * 272 + c * 16) = src[r * 16 + c];
        }
    }
    // ---- prefetch B tile 0 (cp.async) ----
    const __nv_bfloat16* cbS = g_cbS[cb];
    {
        const char* src = reinterpret_cast<const char*>(cbS);
        for (int i = tid; i < 128 * 16; i += 256) {
            int r = i >> 4, c = i & 15;
            CP_ASYNC16(smB0 + r * 272 + c * 16, src + r * 256 + c * 16);
        }
        CP_COMMIT();
    }
    __syncthreads();

    // ---- hoist A fragments: [seg(ah/am)][ks][mt][4] ----
    uint32_t aF[2][4][2][4];
    {
        uint32_t abase = smA + (wm * 32 + (lane & 15)) * 272 + ((lane >> 4) * 16);
        #pragma unroll
        for (int seg = 0; seg < 2; ++seg)
            #pragma unroll
            for (int ks = 0; ks < 4; ++ks)
                #pragma unroll
                for (int mt = 0; mt < 2; ++mt)
                    LDSM_X4(aF[seg][ks][mt], abase + mt * 16 * 272 + (seg * 64 + ks * 16) * 2);
    }

    float v1[4], v2[4];
    int i1[4], i2[4];
    #pragma unroll
    for (int c = 0; c < 4; ++c) { v1[c] = v2[c] = -CUDART_INF_F; i1[c] = i2[c] = 0; }

    const uint32_t browCommon = ((((lane >> 4) & 1) * 8) + (lane & 7)) * 272 + (((lane >> 3) & 1) * 16)
                                + wn * 64 * 272;

    for (int t = 0; t < 64; ++t) {
        // prefetch t+1 into the other buffer (its last compute ended at t-1)
        if (t + 1 < 64) {
            const char* src = reinterpret_cast<const char*>(cbS + (size_t)(t + 1) * 128 * 128);
            uint32_t base = smB0 + ((t + 1) & 1) * SM_TILE;
            for (int i = tid; i < 128 * 16; i += 256) {
                int r = i >> 4, c = i & 15;
                CP_ASYNC16(base + r * 272 + c * 16, src + r * 256 + c * 16);
            }
            CP_COMMIT();
        }
        if (t < 63) { CP_WAIT(1); } else { CP_WAIT(0); }
        __syncthreads();

        float acc[2][8][4] = {};
        const uint32_t brow = smB0 + (t & 1) * SM_TILE + browCommon;
        #pragma unroll
        for (int s = 0; s < 12; ++s) {
            const int segA = (s < 8) ? 0 : 1;
            const int segB = (s >= 4 && s < 8) ? 1 : 0;
            const int ks = s & 3;
            uint32_t bF[4][4];
            #pragma unroll
            for (int p = 0; p < 4; ++p)
                LDSM_X4(bF[p], brow + p * 16 * 272 + (segB * 64 + ks * 16) * 2);
            #pragma unroll
            for (int mt = 0; mt < 2; ++mt)
                #pragma unroll
                for (int nt = 0; nt < 8; ++nt)
                    MMA16816(acc[mt][nt], aF[segA][ks][mt],
                             bF[nt >> 1][(nt & 1) * 2], bF[nt >> 1][(nt & 1) * 2 + 1]);
        }
        __syncthreads();   // buf[t&1] free for the prefetch issued at t+1

        const int colb = t * 128 + wn * 64 + t4 * 2;
        #pragma unroll
        for (int mt = 0; mt < 2; ++mt)
            #pragma unroll
            for (int rh = 0; rh < 2; ++rh) {
                const int c = mt * 2 + rh;
                #pragma unroll
                for (int nt = 0; nt < 8; ++nt)
                    #pragma unroll
                    for (int e = 0; e < 2; ++e) {
                        float v = acc[mt][nt][rh * 2 + e];
                        if (v > v2[c]) {
                            int idx = colb + nt * 8 + e;
                            if (v > v1[c]) { v2[c] = v1[c]; i2[c] = i1[c]; v1[c] = v; i1[c] = idx; }
                            else           { v2[c] = v; i2[c] = idx; }
                        }
                    }
            }
    }

    // ---- gather 16 candidates per row, exact fp32 re-score ----
    __syncthreads();
    int* cand = reinterpret_cast<int*>(dyn);   // overlay (A no longer needed): 128*16*4 = 8KB
    #pragma unroll
    for (int c = 0; c < 4; ++c) {
        int rowl = wm * 32 + (c >> 1) * 16 + g + (c & 1) * 8;
        int slot = wn * 8 + t4 * 2;
        cand[rowl * 16 + slot]     = i1[c];
        cand[rowl * 16 + slot + 1] = i2[c];
    }
    __syncthreads();
    if (tid < 128) {
        const float* fr = &g_featR[cb][(size_t)(rowBase + tid) * VD];
        float fv[VD];
        #pragma unroll
        for (int k = 0; k < VD; ++k) fv[k] = fr[k];
        float bv = -CUDART_INF_F;
        int bi = NCB;
        #pragma unroll 2
        for (int s = 0; s < 16; ++s) {
            int ci = cand[tid * 16 + s];
            const float* cr = &g_cbnR[cb][(size_t)ci * VD];
            float d = 0.f;
            #pragma unroll
            for (int k = 0; k < VD; ++k) d = fmaf(fv[k], cr[k], d);
            if (d > bv || (d == bv && ci < bi)) { bv = d; bi = ci; }
        }
        out[cb * ROWS + rowBase + tid] = (float)bi;
    }
}

// ---------------- launch ----------------
extern "C" void kernel_launch(void* const* d_in, const int* in_sizes, int n_in,
                              void* d_out, int out_size) {
    const float* x = nullptr;
    const float* proj_amp = nullptr;
    const float* proj_phase = nullptr;
    const float* cb_amp = nullptr;
    const float* cb_phase = nullptr;
    for (int i = 0; i < n_in; ++i) {
        const float* p = (const float*)d_in[i];
        int sz = in_sizes[i];
        if (sz == SZ_X) x = p;
        else if (sz == SZ_PROJ) { if (!proj_amp) proj_amp = p; else proj_phase = p; }
        else if (sz == SZ_CB)   { if (!cb_amp)   cb_amp = p;   else cb_phase = p; }
    }
    float* out = (float*)d_out;

    static bool attr_done = false;
    if (!attr_done) {
        cudaFuncSetAttribute(score_kernel, cudaFuncAttributeMaxDynamicSharedMemorySize, SM_DYN);
        attr_done = true;
    }

    build_w_kernel<<<(INPUT_DIM * FFTW + 255) / 256, 256>>>();
    norm_cb_kernel<<<dim3(NCB / 8, 2), 256>>>(cb_amp, cb_phase);
    dft_gemm_kernel<<<dim3(ROWS / 64, 4), 256>>>(x);
    ampphase_kernel<<<(ROWS * NF + 255) / 256, 256>>>();
    proj_kernel<<<dim3(ROWS / 4, 2), 256>>>(proj_amp, proj_phase);
    score_kernel<<<dim3(ROWS / 128, 2), 256, SM_DYN>>>(out);
}

// round 15
// speedup vs baseline: 1.6580x; 1.0749x over previous
#include <cuda_runtime.h>
#include <cuda_bf16.h>
#include <math_constants.h>
#include <cstdint>

// ---------------- Problem constants ----------------
#define ROWS      19456     // B*C*N = 16*19*64
#define INPUT_DIM 200
#define NF        101       // rfft bins
#define FFTW      208       // 2*NF padded (re/im interleaved)
#define VD        64        // VQ dim
#define NCB       8192      // codebook entries

#define SZ_X      (ROWS * INPUT_DIM)
#define SZ_PROJ   (NF * VD)
#define SZ_CB     (NCB * VD)

// ---------------- Device scratch ----------------
__device__ float g_W[INPUT_DIM * FFTW];
__device__ float g_fft[ROWS * FFTW];
__device__ float g_featR[2][ROWS * VD];            // fp32 features (exact rescore)
__device__ float g_cbnR[2][NCB * VD];              // normalized codebooks fp32 (rescore)
__device__ __nv_bfloat16 g_featB[2][ROWS * VD];    // bf16 features
__device__ __nv_bfloat16 g_cbB[2][NCB * VD];       // bf16 normalized codebooks

// ============ base-ISA asm helpers (sm_80+) ============
__device__ __forceinline__ uint32_t smem_u32(const void* p) {
    uint32_t a;
    asm("{ .reg .u64 t; cvta.to.shared.u64 t, %1; cvt.u32.u64 %0, t; }" : "=r"(a) : "l"(p));
    return a;
}
#define CP_ASYNC16(dst, src) \
    asm volatile("cp.async.ca.shared.global [%0], [%1], 16;" :: "r"(dst), "l"(src))
#define CP_COMMIT() asm volatile("cp.async.commit_group;" ::: "memory")
#define CP_WAIT(n)  asm volatile("cp.async.wait_group %0;" :: "n"(n) : "memory")
#define LDSM_X4(r, addr) \
    asm volatile("ldmatrix.sync.aligned.m8n8.x4.shared.b16 {%0,%1,%2,%3}, [%4];" \
        : "=r"((r)[0]), "=r"((r)[1]), "=r"((r)[2]), "=r"((r)[3]) : "r"(addr))
#define MMA16816(d, a, b0, b1) \
    asm volatile("mma.sync.aligned.m16n8k16.row.col.f32.bf16.bf16.f32 " \
        "{%0,%1,%2,%3}, {%4,%5,%6,%7}, {%8,%9}, {%0,%1,%2,%3};" \
        : "+f"((d)[0]), "+f"((d)[1]), "+f"((d)[2]), "+f"((d)[3]) \
        : "r"((a)[0]), "r"((a)[1]), "r"((a)[2]), "r"((a)[3]), "r"(b0), "r"(b1))

// ---------------- K0: DFT matrix (fp64 twiddles) ----------------
__global__ void build_w_kernel() {
    int i = blockIdx.x * blockDim.x + threadIdx.x;
    if (i >= INPUT_DIM * FFTW) return;
    int n = i / FFTW, c = i % FFTW, f = c >> 1;
    float val = 0.f;
    if (f < NF) {
        double s, cs;
        sincospi((double)(n * f) / 100.0, &s, &cs);
        const double scale = 0.070710678118654752440;  // 1/sqrt(200)
        val = (c & 1) ? (float)(-s * scale) : (float)(cs * scale);
    }
    g_W[i] = val;
}

// ---------------- K1: normalize codebooks -> fp32 + bf16 ----------------
__global__ void norm_cb_kernel(const float* __restrict__ cb_amp,
                               const float* __restrict__ cb_phase) {
    int which = blockIdx.y;
    const float* src = which ? cb_phase : cb_amp;
    int warp = threadIdx.x >> 5, lane = threadIdx.x & 31;
    int m = blockIdx.x * 8 + warp;
    float v0 = src[m * VD + lane];
    float v1 = src[m * VD + 32 + lane];
    float s = v0 * v0 + v1 * v1;
    #pragma unroll
    for (int o = 16; o; o >>= 1) s += __shfl_xor_sync(0xffffffffu, s, o);
    float inv = 1.f / sqrtf(s);
    float n0 = v0 * inv, n1 = v1 * inv;
    g_cbnR[which][m * VD + lane]      = n0;
    g_cbnR[which][m * VD + 32 + lane] = n1;
    g_cbB[which][m * VD + lane]      = __float2bfloat16(n0);
    g_cbB[which][m * VD + 32 + lane] = __float2bfloat16(n1);
}

// ---------------- K2: DFT GEMM (fp32 FFMA) ----------------
__global__ void dft_gemm_kernel(const float* __restrict__ x) {
    __shared__ float As[64 * 40];
    __shared__ float Bs[40 * 64];
    int tx = threadIdx.x & 15, ty = threadIdx.x >> 4;
    int rowBase = blockIdx.x * 64, colBase = blockIdx.y * 64;
    float acc[4][4] = {};
    for (int kt = 0; kt < 5; ++kt) {
        int k0 = kt * 40;
        __syncthreads();
        for (int idx = threadIdx.x; idx < 64 * 40; idx += 256) {
            int mm = idx / 40, kk = idx - mm * 40;
            As[idx] = x[(rowBase + mm) * INPUT_DIM + k0 + kk];
        }
        for (int idx = threadIdx.x; idx < 40 * 64; idx += 256) {
            int kk = idx >> 6, nn = idx & 63;
            int c = colBase + nn;
            Bs[idx] = (c < FFTW) ? g_W[(k0 + kk) * FFTW + c] : 0.f;
        }
        __syncthreads();
        #pragma unroll 8
        for (int k = 0; k < 40; ++k) {
            float4 b = *reinterpret_cast<const float4*>(&Bs[k * 64 + tx * 4]);
            float bv[4] = {b.x, b.y, b.z, b.w};
            #pragma unroll
            for (int i = 0; i < 4; ++i) {
                float a = As[(ty * 4 + i) * 40 + k];
                #pragma unroll
                for (int j = 0; j < 4; ++j) acc[i][j] += a * bv[j];
            }
        }
    }
    #pragma unroll
    for (int i = 0; i < 4; ++i) {
        int r = rowBase + ty * 4 + i;
        #pragma unroll
        for (int j = 0; j < 4; ++j) {
            int c = colBase + tx * 4 + j;
            if (c < FFTW) g_fft[r * FFTW + c] = acc[i][j];
        }
    }
}

// ---------------- K3: fused amp/phase + projection -> featR (fp32) + featB (bf16) ----
__global__ void proj_kernel(const float* __restrict__ proj_amp,
                            const float* __restrict__ proj_phase) {
    __shared__ float pjs[NF * VD];
    __shared__ float rows_s[4 * NF];
    int y = blockIdx.y;
    const float* proj = y ? proj_phase : proj_amp;
    int rowBase = blockIdx.x * 4;
    for (int idx = threadIdx.x; idx < NF * VD; idx += 256) pjs[idx] = proj[idx];
    for (int idx = threadIdx.x; idx < 4 * NF; idx += 256) {
        int r = idx / NF, f = idx - r * NF;
        float re = g_fft[(rowBase + r) * FFTW + 2 * f];
        float im = g_fft[(rowBase + r) * FFTW + 2 * f + 1];
        rows_s[idx] = y ? atan2f(im, re) : sqrtf(re * re + im * im);
    }
    __syncthreads();
    int tx = threadIdx.x & 63, ty = threadIdx.x >> 6;
    float acc = 0.f;
    #pragma unroll
    for (int k = 0; k < NF; ++k)
        acc += rows_s[ty * NF + k] * pjs[k * VD + tx];
    int row = rowBase + ty;
    g_featR[y][row * VD + tx] = acc;
    g_featB[y][row * VD + tx] = __float2bfloat16(acc);
}

// ---------------- K4: HMMA bf16 score GEMM + per-thread top4 + exact fp32 rescore ----
// BM=128, BN=64, K=64 (4 k-steps). 8 warps = 4(m) x 2(n), warp tile 32x32.
// Each thread keeps top-4 over its 1024-col slice -> 32 candidates/row, all
// re-scored with exact fp32 dots (index tie-break) = proven-exact semantics.
#define A_STRIDE 144
#define SM_A   (128 * A_STRIDE)          // 18432
#define SM_BT  (64 * A_STRIDE)           // 9216 per buffer
#define SM_DYN (SM_A + 2 * SM_BT)        // 36864

__global__ void __launch_bounds__(256, 2)
score_kernel(float* __restrict__ out) {
    extern __shared__ __align__(16) unsigned char dyn[];
    const int tid = threadIdx.x;
    const int lane = tid & 31, w = tid >> 5;
    const int wm = w & 3, wn = w >> 2;
    const int g = lane >> 2, t4 = lane & 3;
    const int cb = blockIdx.y;
    const int rowBase = blockIdx.x * 128;

    const uint32_t smA = smem_u32(dyn);
    const uint32_t smB0 = smA + SM_A;

    // ---- stage A: 128 rows x 64 bf16 (128B) -> stride 144 ----
    {
        const uint4* src = reinterpret_cast<const uint4*>(&g_featB[cb][(size_t)rowBase * VD]);
        for (int i = tid; i < 128 * 8; i += 256) {
            int r = i >> 3, c = i & 7;
            *reinterpret_cast<uint4*>(dyn + r * A_STRIDE + c * 16) = src[r * 8 + c];
        }
    }
    // ---- prefetch B tile 0 ----
    const char* cbBp = reinterpret_cast<const char*>(g_cbB[cb]);
    {
        for (int i = tid; i < 64 * 8; i += 256) {
            int r = i >> 3, c = i & 7;
            CP_ASYNC16(smB0 + r * A_STRIDE + c * 16, cbBp + r * 128 + c * 16);
        }
        CP_COMMIT();
    }
    __syncthreads();

    // ---- hoist A fragments: [ks][mt][4] ----
    uint32_t aF[4][2][4];
    {
        uint32_t abase = smA + (wm * 32 + (lane & 15)) * A_STRIDE + ((lane >> 4) * 16);
        #pragma unroll
        for (int ks = 0; ks < 4; ++ks)
            #pragma unroll
            for (int mt = 0; mt < 2; ++mt)
                LDSM_X4(aF[ks][mt], abase + mt * 16 * A_STRIDE + ks * 32);
    }

    float tv[4][4];
    int ti[4][4];
    #pragma unroll
    for (int c = 0; c < 4; ++c)
        #pragma unroll
        for (int r = 0; r < 4; ++r) { tv[c][r] = -CUDART_INF_F; ti[c][r] = 0; }

    const uint32_t browCommon = ((((lane >> 4) & 1) * 8) + (lane & 7)) * A_STRIDE
                                + (((lane >> 3) & 1) * 16) + wn * 32 * A_STRIDE;

    for (int t = 0; t < 128; ++t) {
        if (t + 1 < 128) {
            const char* src = cbBp + (size_t)(t + 1) * 64 * 128;
            uint32_t base = smB0 + ((t + 1) & 1) * SM_BT;
            for (int i = tid; i < 64 * 8; i += 256) {
                int r = i >> 3, c = i & 7;
                CP_ASYNC16(base + r * A_STRIDE + c * 16, src + r * 128 + c * 16);
            }
            CP_COMMIT();
        }
        if (t < 127) { CP_WAIT(1); } else { CP_WAIT(0); }
        __syncthreads();

        float acc[2][4][4] = {};
        const uint32_t brow = smB0 + (t & 1) * SM_BT + browCommon;
        #pragma unroll
        for (int ks = 0; ks < 4; ++ks) {
            uint32_t bF[2][4];
            #pragma unroll
            for (int p = 0; p < 2; ++p)
                LDSM_X4(bF[p], brow + p * 16 * A_STRIDE + ks * 32);
            #pragma unroll
            for (int mt = 0; mt < 2; ++mt)
                #pragma unroll
                for (int nt = 0; nt < 4; ++nt)
                    MMA16816(acc[mt][nt], aF[ks][mt],
                             bF[nt >> 1][(nt & 1) * 2], bF[nt >> 1][(nt & 1) * 2 + 1]);
        }
        __syncthreads();   // buf[t&1] free for prefetch at t+1

        const int colb = t * 64 + wn * 32 + t4 * 2;
        #pragma unroll
        for (int mt = 0; mt < 2; ++mt)
            #pragma unroll
            for (int rh = 0; rh < 2; ++rh) {
                const int c = mt * 2 + rh;
                #pragma unroll
                for (int nt = 0; nt < 4; ++nt)
                    #pragma unroll
                    for (int e = 0; e < 2; ++e) {
                        float v = acc[mt][nt][rh * 2 + e];
                        if (v > tv[c][3]) {
                            int idx = colb + nt * 8 + e;
                            if (v > tv[c][1]) {
                                if (v > tv[c][0]) {
                                    tv[c][3] = tv[c][2]; ti[c][3] = ti[c][2];
                                    tv[c][2] = tv[c][1]; ti[c][2] = ti[c][1];
                                    tv[c][1] = tv[c][0]; ti[c][1] = ti[c][0];
                                    tv[c][0] = v; ti[c][0] = idx;
                                } else {
                                    tv[c][3] = tv[c][2]; ti[c][3] = ti[c][2];
                                    tv[c][2] = tv[c][1]; ti[c][2] = ti[c][1];
                                    tv[c][1] = v; ti[c][1] = idx;
                                }
                            } else {
                                if (v > tv[c][2]) {
                                    tv[c][3] = tv[c][2]; ti[c][3] = ti[c][2];
                                    tv[c][2] = v; ti[c][2] = idx;
                                } else {
                                    tv[c][3] = v; ti[c][3] = idx;
                                }
                            }
                        }
                    }
            }
    }

    // ---- gather 32 candidates/row, exact fp32 rescore (2 threads per row) ----
    __syncthreads();
    int* cand = reinterpret_cast<int*>(dyn);   // 128*32*4 = 16KB overlay
    #pragma unroll
    for (int c = 0; c < 4; ++c) {
        int rowl = wm * 32 + (c >> 1) * 16 + g + (c & 1) * 8;
        int slot = (wn * 4 + t4) * 4;
        #pragma unroll
        for (int r = 0; r < 4; ++r)
            cand[rowl * 32 + slot + r] = ti[c][r];
    }
    __syncthreads();
    {
        int row = tid >> 1, half = tid & 1;
        const float* fr = &g_featR[cb][(size_t)(rowBase + row) * VD];
        float fv[VD];
        #pragma unroll
        for (int k = 0; k < VD; ++k) fv[k] = fr[k];
        float bv = -CUDART_INF_F;
        int bi = NCB;
        #pragma unroll 2
        for (int s = 0; s < 16; ++s) {
            int ci = cand[row * 32 + half * 16 + s];
            const float* cr = &g_cbnR[cb][(size_t)ci * VD];
            float d = 0.f;
            #pragma unroll
            for (int k = 0; k < VD; ++k) d = fmaf(fv[k], cr[k], d);
            if (d > bv || (d == bv && ci < bi)) { bv = d; bi = ci; }
        }
        float ov = __shfl_xor_sync(0xffffffffu, bv, 1);
        int   oi = __shfl_xor_sync(0xffffffffu, bi, 1);
        if (ov > bv || (ov == bv && oi < bi)) { bv = ov; bi = oi; }
        if (half == 0) out[cb * ROWS + rowBase + row] = (float)bi;
    }
}

// ---------------- launch ----------------
extern "C" void kernel_launch(void* const* d_in, const int* in_sizes, int n_in,
                              void* d_out, int out_size) {
    const float* x = nullptr;
    const float* proj_amp = nullptr;
    const float* proj_phase = nullptr;
    const float* cb_amp = nullptr;
    const float* cb_phase = nullptr;
    for (int i = 0; i < n_in; ++i) {
        const float* p = (const float*)d_in[i];
        int sz = in_sizes[i];
        if (sz == SZ_X) x = p;
        else if (sz == SZ_PROJ) { if (!proj_amp) proj_amp = p; else proj_phase = p; }
        else if (sz == SZ_CB)   { if (!cb_amp)   cb_amp = p;   else cb_phase = p; }
    }
    float* out = (float*)d_out;

    build_w_kernel<<<(INPUT_DIM * FFTW + 255) / 256, 256>>>();
    norm_cb_kernel<<<dim3(NCB / 8, 2), 256>>>(cb_amp, cb_phase);
    dft_gemm_kernel<<<dim3(ROWS / 64, 4), 256>>>(x);
    proj_kernel<<<dim3(ROWS / 4, 2), 256>>>(proj_amp, proj_phase);
    score_kernel<<<dim3(ROWS / 128, 2), 256, SM_DYN>>>(out);
}